// round 10
// baseline (speedup 1.0000x reference)
#include <cuda_runtime.h>
#include <cuda_fp16.h>

#define IMG_H 512
#define IMG_W 512
#define HW (IMG_H * IMG_W)

// Channel-last fp16 staging: [b][z][y][x][32]  (1 MB each)
__device__ __half g1h[8 * 8 * 16 * 16 * 32];
__device__ __half g2h[8 * 8 * 16 * 16 * 32];   // 27 real channels + 5 zero pad

__global__ __launch_bounds__(256) void transpose_grids_h(
    const float* __restrict__ g1, const float* __restrict__ g2)
{
    const int i = blockIdx.x * 256 + threadIdx.x;
    if (i < 8 * 32 * 8 * 256) {
        const int x = i & 15, y = (i >> 4) & 15, z = (i >> 8) & 7;
        const int c = (i >> 11) & 31, b = i >> 16;
        g1h[(((b * 8 + z) * 16 + y) * 16 + x) * 32 + c] = __float2half(g1[i]);
    }
    if (i < 8 * 27 * 8 * 256) {
        const int x = i & 15, y = (i >> 4) & 15, z = (i >> 8) & 7;
        const int t = i >> 11;
        const int c = t % 27, b = t / 27;
        g2h[(((b * 8 + z) * 16 + y) * 16 + x) * 32 + c] = __float2half(g2[i]);
    }
    if (i < 8 * 8 * 256) {
#pragma unroll
        for (int c = 27; c < 32; c++) g2h[i * 32 + c] = __float2half(0.0f);
    }
}

__device__ __forceinline__ float tanh_approx(float x) {
    float y;
    asm("tanh.approx.f32 %0, %1;" : "=f"(y) : "f"(x));
    return y;
}
typedef unsigned long long u64;
__device__ __forceinline__ u64 pk2(float lo, float hi) {
    u64 r;
    asm("mov.b64 %0, {%1, %2};" : "=l"(r) : "f"(lo), "f"(hi));
    return r;
}
__device__ __forceinline__ void upk2(float& lo, float& hi, u64 p) {
    asm("mov.b64 {%0, %1}, %2;" : "=f"(lo), "=f"(hi) : "l"(p));
}
__device__ __forceinline__ u64 fma2q(u64 a, u64 b, u64 c) {
    u64 d;
    asm("fma.rn.f32x2 %0, %1, %2, %3;" : "=l"(d) : "l"(a), "l"(b), "l"(c));
    return d;
}
__device__ __forceinline__ u64 h2f2(__half2 h) {
    u64 r;
    unsigned int u = *(unsigned int*)&h;
    asm("{\n\t.reg .b16 l, h;\n\t.reg .f32 fl, fh;\n\t"
        "mov.b32 {l, h}, %1;\n\t"
        "cvt.f32.f16 fl, l;\n\t"
        "cvt.f32.f16 fh, h;\n\t"
        "mov.b64 %0, {fl, fh};\n\t}" : "=l"(r) : "r"(u));
    return r;
}
__device__ __forceinline__ __half2 u2h(unsigned int u) { return *(__half2*)&u; }
__device__ __forceinline__ __half2 lerp2(__half2 a, __half2 b, __half2 w) {
    return __hfma2(w, __hsub2(b, a), a);
}

// smem tile geometry (uint4 units): [grid][yc(2)][z(8)][xc(9)][j(4)]
//   xc stride = 4, z stride = 37 (36 + 1 pad -> z maps to distinct bank-groups),
//   yc stride = 296, grid stride = 592. Total 1184 uint4 = 18.5 KB.
#define U4_Z 37
#define U4_Y (8 * U4_Z)      // 296
#define U4_G (2 * U4_Y)      // 592

__global__ __launch_bounds__(256, 4) void bgrid_fused_kernel(
    const float* __restrict__ src,
    const float* __restrict__ w1, const float* __restrict__ b1,
    const float* __restrict__ w2, const float* __restrict__ b2,
    const float* __restrict__ w3, const float* __restrict__ b3,
    const float* __restrict__ w4, const float* __restrict__ b4,
    float* __restrict__ out)
{
    __shared__ uint4 sg[2 * U4_G];          // 18944 B grid tile (both grids)
    __shared__ float2 sp1[8][3];
    __shared__ float2 b1p[8];
    __shared__ float  sw2[16];
    __shared__ float2 sp3[8][8];
    __shared__ float2 b3p[8];
    __shared__ float  sw4[16];
    __shared__ float  sb2s, sb4s;

    const int tid = threadIdx.x;
    if (tid < 24) {
        const int op = tid / 3, jj = tid - op * 3;
        sp1[op][jj] = make_float2(w1[(2 * op) * 3 + jj], w1[(2 * op + 1) * 3 + jj]);
    }
    if (tid < 8) {
        b1p[tid] = make_float2(b1[2 * tid], b1[2 * tid + 1]);
        b3p[tid] = make_float2(b3[2 * tid], b3[2 * tid + 1]);
    }
    if (tid < 16) { sw2[tid] = w2[tid]; sw4[tid] = w4[tid]; }
    if (tid < 64) {
        const int op = tid >> 3, q = tid & 7;
        sp3[op][q] = make_float2(w3[(2 * op) * 8 + q], w3[(2 * op + 1) * 8 + q]);
    }
    if (tid == 0) { sb2s = b2[0]; sb4s = b4[0]; }

    const int idx = blockIdx.x * 256 + tid;
    const int px = idx & 511;
    const int py = (idx >> 9) & 511;        // constant within block
    const int pb = idx >> 18;               // constant within block

    // block-wide lattice window: x spans exactly 9 corners, y spans 2
    const int xbase = (blockIdx.x & 1) * 256;
    const int x0min = (xbase * 15) >> 9;    // 0 or 7
    const int y0 = (py * 15) >> 9;          // == (int)fy exactly

    // ---- stage grid tile: 1152 uint4 chunks, coalesced from g1h/g2h ----
    {
        const __half* g1b = g1h + pb * 65536;
        const __half* g2b = g2h + pb * 65536;
#pragma unroll
        for (int i = tid; i < 1152; i += 256) {
            const int j = i & 3;
            int t = i >> 2;                  // 0..287
            const int gsel = (t >= 144);
            if (gsel) t -= 144;
            const int xc = t % 9;
            const int u = t / 9;             // 0..15
            const int z = u & 7;
            const int yc = u >> 3;
            const __half* gs = gsel ? g2b : g1b;
            const uint4 v = *((const uint4*)(gs + ((z * 16 + (y0 + yc)) * 16 +
                                                   (x0min + xc)) * 32) + j);
            sg[gsel * U4_G + yc * U4_Y + z * U4_Z + xc * 4 + j] = v;
        }
    }
    __syncthreads();

    // ---- src pixel ----
    const float* srcp = src + (pb * 3) * HW + py * IMG_W + px;
    const float s0 = srcp[0];
    const float s1 = srcp[HW];
    const float s2 = srcp[2 * HW];
    const u64 sap[4] = {pk2(s0, s0), pk2(s1, s1), pk2(s2, s2), pk2(1.0f, 1.0f)};

    // ---- guide NN #1 ----
    float g = sb2s;
#pragma unroll
    for (int op = 0; op < 8; op++) {
        u64 t2 = *(const u64*)&b1p[op];
        t2 = fma2q(sap[0], *(const u64*)&sp1[op][0], t2);
        t2 = fma2q(sap[1], *(const u64*)&sp1[op][1], t2);
        t2 = fma2q(sap[2], *(const u64*)&sp1[op][2], t2);
        float lo, hi; upk2(lo, hi, t2);
        lo = fmaxf(lo, 0.0f); hi = fmaxf(hi, 0.0f);
        g = fmaf(sw2[2 * op], lo, g);
        g = fmaf(sw2[2 * op + 1], hi, g);
    }
    g = tanh_approx(g);

    // ---- xy lattice ----
    const float fx = (float)px * (15.0f / 512.0f);
    const float fy = (float)py * (15.0f / 512.0f);
    const int x0 = (int)fx;
    const float wx = fx - (float)x0;
    const float wy = fy - (float)y0;
    const __half2 wxh = __float2half2_rn(wx);
    const __half2 wyh = __float2half2_rn(wy);
    const int xg = x0 - x0min;              // 0..8
    // corner uint4 bases within the smem tile
    int cb4[2][2];
#pragma unroll
    for (int yi = 0; yi < 2; yi++)
#pragma unroll
        for (int xi = 0; xi < 2; xi++)
            cb4[yi][xi] = yi * U4_Y + (xg + xi) * 4;

    // ---- z for slice 1 ----
    float fz = fminf(fmaxf((g + 1.0f) * 3.5f, 0.0f), 7.0f);
    int z0 = (int)fz;
    if (z0 > 7) z0 = 7;
    int z1 = min(z0 + 1, 7);
    __half2 wzh = __float2half2_rn(fz - (float)z0);

    // ---- slice grid1 from smem: fp16 trilerp tree -> hidp[4] ----
    u64 hidp[4];
#pragma unroll
    for (int e = 0; e < 4; e++) hidp[e] = pk2(0.0f, 0.0f);
    {
        const int zo0 = z0 * U4_Z, zo1 = z1 * U4_Z;
#pragma unroll
        for (int j = 0; j < 4; j++) {
            __half2 zl[2][2][4];
#pragma unroll
            for (int yi = 0; yi < 2; yi++) {
#pragma unroll
                for (int xi = 0; xi < 2; xi++) {
                    const uint4 a = sg[cb4[yi][xi] + zo0 + j];
                    const uint4 b = sg[cb4[yi][xi] + zo1 + j];
                    zl[yi][xi][0] = lerp2(u2h(a.x), u2h(b.x), wzh);
                    zl[yi][xi][1] = lerp2(u2h(a.y), u2h(b.y), wzh);
                    zl[yi][xi][2] = lerp2(u2h(a.z), u2h(b.z), wzh);
                    zl[yi][xi][3] = lerp2(u2h(a.w), u2h(b.w), wzh);
                }
            }
#pragma unroll
            for (int e = 0; e < 4; e++) {
                const __half2 t0 = lerp2(zl[0][0][e], zl[0][1][e], wxh);
                const __half2 t1 = lerp2(zl[1][0][e], zl[1][1][e], wxh);
                const __half2 d  = lerp2(t0, t1, wyh);
                hidp[e] = fma2q(h2f2(d), sap[j], hidp[e]);
            }
        }
    }
    float hid[8];
#pragma unroll
    for (int e = 0; e < 4; e++) {
        float lo, hi; upk2(lo, hi, hidp[e]);
        hid[2 * e]     = fmaxf(lo, 0.0f);
        hid[2 * e + 1] = fmaxf(hi, 0.0f);
    }

    // ---- guide NN #2 ----
    u64 hd[8];
#pragma unroll
    for (int q = 0; q < 8; q++) hd[q] = pk2(hid[q], hid[q]);
    float g2a = sb4s;
#pragma unroll
    for (int op = 0; op < 8; op++) {
        u64 t2 = *(const u64*)&b3p[op];
#pragma unroll
        for (int q = 0; q < 8; q++)
            t2 = fma2q(hd[q], *(const u64*)&sp3[op][q], t2);
        float lo, hi; upk2(lo, hi, t2);
        lo = fmaxf(lo, 0.0f); hi = fmaxf(hi, 0.0f);
        g2a = fmaf(sw4[2 * op], lo, g2a);
        g2a = fmaf(sw4[2 * op + 1], hi, g2a);
    }
    g2a = tanh_approx(g2a);

    // ---- z for slice 2 ----
    fz = fminf(fmaxf((g2a + 1.0f) * 3.5f, 0.0f), 7.0f);
    z0 = (int)fz;
    if (z0 > 7) z0 = 7;
    z1 = min(z0 + 1, 7);
    wzh = __float2half2_rn(fz - (float)z0);

    // ---- slice grid2 from smem: fp16 trilerp tree -> out[3] ----
    float m2[11];
#pragma unroll
    for (int q = 0; q < 8; q++) m2[q] = hid[q];
    m2[8] = 1.0f; m2[9] = 0.0f; m2[10] = 0.0f;

    float r[3] = {0.0f, 0.0f, 0.0f};
    {
        const uint4* sg2 = sg + U4_G;
        const int zo0 = z0 * U4_Z, zo1 = z1 * U4_Z;
#pragma unroll
        for (int j = 0; j < 4; j++) {
            __half2 zl[2][2][4];
#pragma unroll
            for (int yi = 0; yi < 2; yi++) {
#pragma unroll
                for (int xi = 0; xi < 2; xi++) {
                    const uint4 a = sg2[cb4[yi][xi] + zo0 + j];
                    const uint4 b = sg2[cb4[yi][xi] + zo1 + j];
                    zl[yi][xi][0] = lerp2(u2h(a.x), u2h(b.x), wzh);
                    zl[yi][xi][1] = lerp2(u2h(a.y), u2h(b.y), wzh);
                    zl[yi][xi][2] = lerp2(u2h(a.z), u2h(b.z), wzh);
                    zl[yi][xi][3] = lerp2(u2h(a.w), u2h(b.w), wzh);
                }
            }
#pragma unroll
            for (int e = 0; e < 4; e++) {
                const __half2 t0 = lerp2(zl[0][0][e], zl[0][1][e], wxh);
                const __half2 t1 = lerp2(zl[1][0][e], zl[1][1][e], wxh);
                const __half2 d  = lerp2(t0, t1, wyh);
                float lo, hi; upk2(lo, hi, h2f2(d));
                const int c = 8 * j + 2 * e;
                r[c % 3]       = fmaf(lo, m2[c / 3], r[c % 3]);
                r[(c + 1) % 3] = fmaf(hi, m2[(c + 1) / 3], r[(c + 1) % 3]);
            }
        }
    }

    float* outp = out + (pb * 3) * HW + py * IMG_W + px;
    outp[0]      = r[0];
    outp[HW]     = r[1];
    outp[2 * HW] = r[2];
}

extern "C" void kernel_launch(void* const* d_in, const int* in_sizes, int n_in,
                              void* d_out, int out_size) {
    const float* src   = (const float*)d_in[0];
    const float* grid1 = (const float*)d_in[1];
    const float* grid2 = (const float*)d_in[2];
    const float* w1    = (const float*)d_in[3];
    const float* b1    = (const float*)d_in[4];
    const float* w2    = (const float*)d_in[5];
    const float* b2    = (const float*)d_in[6];
    const float* w3    = (const float*)d_in[7];
    const float* b3    = (const float*)d_in[8];
    const float* w4    = (const float*)d_in[9];
    const float* b4    = (const float*)d_in[10];
    float* out = (float*)d_out;

    {
        const int total = 8 * 32 * 8 * 256;
        transpose_grids_h<<<(total + 255) / 256, 256>>>(grid1, grid2);
    }
    const int total = 8 * IMG_H * IMG_W;
    bgrid_fused_kernel<<<total / 256, 256>>>(src,
                                             w1, b1, w2, b2, w3, b3, w4, b4,
                                             out);
}

// round 11
// speedup vs baseline: 1.0438x; 1.0438x over previous
#include <cuda_runtime.h>
#include <cuda_fp16.h>

#define IMG_H 512
#define IMG_W 512
#define HW (IMG_H * IMG_W)

// Channel-last fp16 staging: [b][z][y][x][32]  (1 MB each)
__device__ __half g1h[8 * 8 * 16 * 16 * 32];
__device__ __half g2h[8 * 8 * 16 * 16 * 32];   // 27 real channels + 5 zero pad

__global__ __launch_bounds__(256) void transpose_grids_h(
    const float* __restrict__ g1, const float* __restrict__ g2)
{
    const int i = blockIdx.x * 256 + threadIdx.x;
    if (i < 8 * 32 * 8 * 256) {
        const int x = i & 15, y = (i >> 4) & 15, z = (i >> 8) & 7;
        const int c = (i >> 11) & 31, b = i >> 16;
        g1h[(((b * 8 + z) * 16 + y) * 16 + x) * 32 + c] = __float2half(g1[i]);
    }
    if (i < 8 * 27 * 8 * 256) {
        const int x = i & 15, y = (i >> 4) & 15, z = (i >> 8) & 7;
        const int t = i >> 11;
        const int c = t % 27, b = t / 27;
        g2h[(((b * 8 + z) * 16 + y) * 16 + x) * 32 + c] = __float2half(g2[i]);
    }
    if (i < 8 * 8 * 256) {
#pragma unroll
        for (int c = 27; c < 32; c++) g2h[i * 32 + c] = __float2half(0.0f);
    }
}

__device__ __forceinline__ float tanh_approx(float x) {
    float y;
    asm("tanh.approx.f32 %0, %1;" : "=f"(y) : "f"(x));
    return y;
}
typedef unsigned long long u64;
__device__ __forceinline__ u64 pk2(float lo, float hi) {
    u64 r;
    asm("mov.b64 %0, {%1, %2};" : "=l"(r) : "f"(lo), "f"(hi));
    return r;
}
__device__ __forceinline__ void upk2(float& lo, float& hi, u64 p) {
    asm("mov.b64 {%0, %1}, %2;" : "=f"(lo), "=f"(hi) : "l"(p));
}
__device__ __forceinline__ u64 fma2q(u64 a, u64 b, u64 c) {
    u64 d;
    asm("fma.rn.f32x2 %0, %1, %2, %3;" : "=l"(d) : "l"(a), "l"(b), "l"(c));
    return d;
}
__device__ __forceinline__ u64 add2q(u64 a, u64 b) {
    u64 d;
    asm("add.rn.f32x2 %0, %1, %2;" : "=l"(d) : "l"(a), "l"(b));
    return d;
}
__device__ __forceinline__ u64 h2f2(__half2 h) {
    u64 r;
    unsigned int u = *(unsigned int*)&h;
    asm("{\n\t.reg .b16 l, h;\n\t.reg .f32 fl, fh;\n\t"
        "mov.b32 {l, h}, %1;\n\t"
        "cvt.f32.f16 fl, l;\n\t"
        "cvt.f32.f16 fh, h;\n\t"
        "mov.b64 %0, {fl, fh};\n\t}" : "=l"(r) : "r"(u));
    return r;
}
__device__ __forceinline__ __half2 u2h(unsigned int u) { return *(__half2*)&u; }

// bilinear (fp16, near-exact weights) at z0 and z1, then z-lerp in f32x2.
// Returns packed f32x2 of the trilinear result for 2 channels.
__device__ __forceinline__ u64 xyz_interp(
    unsigned a00, unsigned a01, unsigned a10, unsigned a11,
    unsigned b00, unsigned b01, unsigned b10, unsigned b11,
    __half2 w00h, __half2 w01h, __half2 w10h, __half2 w11h, u64 wzq)
{
    __half2 s0 = __hmul2(w00h, u2h(a00));
    s0 = __hfma2(w01h, u2h(a01), s0);
    s0 = __hfma2(w10h, u2h(a10), s0);
    s0 = __hfma2(w11h, u2h(a11), s0);
    __half2 s1 = __hmul2(w00h, u2h(b00));
    s1 = __hfma2(w01h, u2h(b01), s1);
    s1 = __hfma2(w10h, u2h(b10), s1);
    s1 = __hfma2(w11h, u2h(b11), s1);
    const u64 A = h2f2(s0);
    const u64 B = h2f2(s1);
    const u64 d = add2q(B, A ^ 0x8000000080000000ULL);  // exact B - A
    return fma2q(wzq, d, A);                            // A + wz*(B-A), wz fp32
}

__global__ __launch_bounds__(256, 4) void bgrid_fused_kernel(
    const float* __restrict__ src,
    const float* __restrict__ w1, const float* __restrict__ b1,
    const float* __restrict__ w2, const float* __restrict__ b2,
    const float* __restrict__ w3, const float* __restrict__ b3,
    const float* __restrict__ w4, const float* __restrict__ b4,
    float* __restrict__ out)
{
    __shared__ float2 sp1[8][3];
    __shared__ float2 b1p[8];
    __shared__ float  sw2[16];
    __shared__ float2 sp3[8][8];
    __shared__ float2 b3p[8];
    __shared__ float  sw4[16];
    __shared__ float  sb2s, sb4s;

    const int tid = threadIdx.x;
    if (tid < 24) {
        const int op = tid / 3, jj = tid - op * 3;
        sp1[op][jj] = make_float2(w1[(2 * op) * 3 + jj], w1[(2 * op + 1) * 3 + jj]);
    }
    if (tid < 8) {
        b1p[tid] = make_float2(b1[2 * tid], b1[2 * tid + 1]);
        b3p[tid] = make_float2(b3[2 * tid], b3[2 * tid + 1]);
    }
    if (tid < 16) { sw2[tid] = w2[tid]; sw4[tid] = w4[tid]; }
    if (tid < 64) {
        const int op = tid >> 3, q = tid & 7;
        sp3[op][q] = make_float2(w3[(2 * op) * 8 + q], w3[(2 * op + 1) * 8 + q]);
    }
    if (tid == 0) { sb2s = b2[0]; sb4s = b4[0]; }
    __syncthreads();

    const int idx = blockIdx.x * 256 + tid;
    const int px = idx & 511;
    const int py = (idx >> 9) & 511;
    const int pb = idx >> 18;

    // ---- src pixel ----
    const float* srcp = src + (pb * 3) * HW + py * IMG_W + px;
    const float s0 = srcp[0];
    const float s1 = srcp[HW];
    const float s2 = srcp[2 * HW];
    const u64 sap[4] = {pk2(s0, s0), pk2(s1, s1), pk2(s2, s2), pk2(1.0f, 1.0f)};

    // ---- guide NN #1 ----
    float g = sb2s;
#pragma unroll
    for (int op = 0; op < 8; op++) {
        u64 t2 = *(const u64*)&b1p[op];
        t2 = fma2q(sap[0], *(const u64*)&sp1[op][0], t2);
        t2 = fma2q(sap[1], *(const u64*)&sp1[op][1], t2);
        t2 = fma2q(sap[2], *(const u64*)&sp1[op][2], t2);
        float lo, hi; upk2(lo, hi, t2);
        lo = fmaxf(lo, 0.0f); hi = fmaxf(hi, 0.0f);
        g = fmaf(sw2[2 * op], lo, g);
        g = fmaf(sw2[2 * op + 1], hi, g);
    }
    g = tanh_approx(g);

    // ---- xy lattice: wx, wy are exact multiples of 1/512 -> exact in fp16 ----
    const float fx = (float)px * (15.0f / 512.0f);
    const float fy = (float)py * (15.0f / 512.0f);
    const int x0 = (int)fx;
    const int y0 = (int)fy;
    const float wx = fx - (float)x0;
    const float wy = fy - (float)y0;
    // bilinear weights: exact products in fp32, one rounding to fp16
    const __half2 w00h = __float2half2_rn((1.0f - wy) * (1.0f - wx));
    const __half2 w01h = __float2half2_rn((1.0f - wy) * wx);
    const __half2 w10h = __float2half2_rn(wy * (1.0f - wx));
    const __half2 w11h = __float2half2_rn(wy * wx);

    const __half* gb1 = g1h + pb * 65536;
    const int ob00 = ((y0) * 16 + x0) * 32;
    const int ob01 = ob00 + 32;
    const int ob10 = ob00 + 512;
    const int ob11 = ob00 + 544;

    // ---- z for slice 1 ----
    float fz = fminf(fmaxf((g + 1.0f) * 3.5f, 0.0f), 7.0f);
    int z0 = (int)fz;
    if (z0 > 7) z0 = 7;
    int z1 = min(z0 + 1, 7);
    u64 wzq = pk2(fz - (float)z0, fz - (float)z0);

    // ---- slice grid1: xy fp16 weighted sum, z-lerp f32x2 -> hidp[4] ----
    u64 hidp[4];
#pragma unroll
    for (int e = 0; e < 4; e++) hidp[e] = pk2(0.0f, 0.0f);
    {
        const int zo0 = z0 * 8192, zo1 = z1 * 8192;
#pragma unroll
        for (int j = 0; j < 4; j++) {
            const uint4 a00 = __ldg((const uint4*)(gb1 + ob00 + zo0) + j);
            const uint4 a01 = __ldg((const uint4*)(gb1 + ob01 + zo0) + j);
            const uint4 a10 = __ldg((const uint4*)(gb1 + ob10 + zo0) + j);
            const uint4 a11 = __ldg((const uint4*)(gb1 + ob11 + zo0) + j);
            const uint4 b00 = __ldg((const uint4*)(gb1 + ob00 + zo1) + j);
            const uint4 b01 = __ldg((const uint4*)(gb1 + ob01 + zo1) + j);
            const uint4 b10 = __ldg((const uint4*)(gb1 + ob10 + zo1) + j);
            const uint4 b11 = __ldg((const uint4*)(gb1 + ob11 + zo1) + j);
            u64 v;
            v = xyz_interp(a00.x, a01.x, a10.x, a11.x, b00.x, b01.x, b10.x, b11.x,
                           w00h, w01h, w10h, w11h, wzq);
            hidp[0] = fma2q(v, sap[j], hidp[0]);
            v = xyz_interp(a00.y, a01.y, a10.y, a11.y, b00.y, b01.y, b10.y, b11.y,
                           w00h, w01h, w10h, w11h, wzq);
            hidp[1] = fma2q(v, sap[j], hidp[1]);
            v = xyz_interp(a00.z, a01.z, a10.z, a11.z, b00.z, b01.z, b10.z, b11.z,
                           w00h, w01h, w10h, w11h, wzq);
            hidp[2] = fma2q(v, sap[j], hidp[2]);
            v = xyz_interp(a00.w, a01.w, a10.w, a11.w, b00.w, b01.w, b10.w, b11.w,
                           w00h, w01h, w10h, w11h, wzq);
            hidp[3] = fma2q(v, sap[j], hidp[3]);
        }
    }
    float hid[8];
#pragma unroll
    for (int e = 0; e < 4; e++) {
        float lo, hi; upk2(lo, hi, hidp[e]);
        hid[2 * e]     = fmaxf(lo, 0.0f);
        hid[2 * e + 1] = fmaxf(hi, 0.0f);
    }

    // ---- guide NN #2 ----
    u64 hd[8];
#pragma unroll
    for (int q = 0; q < 8; q++) hd[q] = pk2(hid[q], hid[q]);
    float g2a = sb4s;
#pragma unroll
    for (int op = 0; op < 8; op++) {
        u64 t2 = *(const u64*)&b3p[op];
#pragma unroll
        for (int q = 0; q < 8; q++)
            t2 = fma2q(hd[q], *(const u64*)&sp3[op][q], t2);
        float lo, hi; upk2(lo, hi, t2);
        lo = fmaxf(lo, 0.0f); hi = fmaxf(hi, 0.0f);
        g2a = fmaf(sw4[2 * op], lo, g2a);
        g2a = fmaf(sw4[2 * op + 1], hi, g2a);
    }
    g2a = tanh_approx(g2a);

    // ---- z for slice 2 ----
    fz = fminf(fmaxf((g2a + 1.0f) * 3.5f, 0.0f), 7.0f);
    z0 = (int)fz;
    if (z0 > 7) z0 = 7;
    z1 = min(z0 + 1, 7);
    wzq = pk2(fz - (float)z0, fz - (float)z0);

    // ---- slice grid2 -> out[3] ----
    float m2[11];
#pragma unroll
    for (int q = 0; q < 8; q++) m2[q] = hid[q];
    m2[8] = 1.0f; m2[9] = 0.0f; m2[10] = 0.0f;

    float r[3] = {0.0f, 0.0f, 0.0f};
    {
        const __half* gb2 = g2h + pb * 65536;
        const int zo0 = z0 * 8192, zo1 = z1 * 8192;
#pragma unroll
        for (int j = 0; j < 4; j++) {
            const uint4 a00 = __ldg((const uint4*)(gb2 + ob00 + zo0) + j);
            const uint4 a01 = __ldg((const uint4*)(gb2 + ob01 + zo0) + j);
            const uint4 a10 = __ldg((const uint4*)(gb2 + ob10 + zo0) + j);
            const uint4 a11 = __ldg((const uint4*)(gb2 + ob11 + zo0) + j);
            const uint4 b00 = __ldg((const uint4*)(gb2 + ob00 + zo1) + j);
            const uint4 b01 = __ldg((const uint4*)(gb2 + ob01 + zo1) + j);
            const uint4 b10 = __ldg((const uint4*)(gb2 + ob10 + zo1) + j);
            const uint4 b11 = __ldg((const uint4*)(gb2 + ob11 + zo1) + j);
            float lo, hi;
            u64 v;
            {
                v = xyz_interp(a00.x, a01.x, a10.x, a11.x, b00.x, b01.x, b10.x, b11.x,
                               w00h, w01h, w10h, w11h, wzq);
                upk2(lo, hi, v);
                const int c = 8 * j;
                r[c % 3]       = fmaf(lo, m2[c / 3], r[c % 3]);
                r[(c + 1) % 3] = fmaf(hi, m2[(c + 1) / 3], r[(c + 1) % 3]);
            }
            {
                v = xyz_interp(a00.y, a01.y, a10.y, a11.y, b00.y, b01.y, b10.y, b11.y,
                               w00h, w01h, w10h, w11h, wzq);
                upk2(lo, hi, v);
                const int c = 8 * j + 2;
                r[c % 3]       = fmaf(lo, m2[c / 3], r[c % 3]);
                r[(c + 1) % 3] = fmaf(hi, m2[(c + 1) / 3], r[(c + 1) % 3]);
            }
            {
                v = xyz_interp(a00.z, a01.z, a10.z, a11.z, b00.z, b01.z, b10.z, b11.z,
                               w00h, w01h, w10h, w11h, wzq);
                upk2(lo, hi, v);
                const int c = 8 * j + 4;
                r[c % 3]       = fmaf(lo, m2[c / 3], r[c % 3]);
                r[(c + 1) % 3] = fmaf(hi, m2[(c + 1) / 3], r[(c + 1) % 3]);
            }
            {
                v = xyz_interp(a00.w, a01.w, a10.w, a11.w, b00.w, b01.w, b10.w, b11.w,
                               w00h, w01h, w10h, w11h, wzq);
                upk2(lo, hi, v);
                const int c = 8 * j + 6;
                r[c % 3]       = fmaf(lo, m2[c / 3], r[c % 3]);
                r[(c + 1) % 3] = fmaf(hi, m2[(c + 1) / 3], r[(c + 1) % 3]);
            }
        }
    }

    float* outp = out + (pb * 3) * HW + py * IMG_W + px;
    outp[0]      = r[0];
    outp[HW]     = r[1];
    outp[2 * HW] = r[2];
}

extern "C" void kernel_launch(void* const* d_in, const int* in_sizes, int n_in,
                              void* d_out, int out_size) {
    const float* src   = (const float*)d_in[0];
    const float* grid1 = (const float*)d_in[1];
    const float* grid2 = (const float*)d_in[2];
    const float* w1    = (const float*)d_in[3];
    const float* b1    = (const float*)d_in[4];
    const float* w2    = (const float*)d_in[5];
    const float* b2    = (const float*)d_in[6];
    const float* w3    = (const float*)d_in[7];
    const float* b3    = (const float*)d_in[8];
    const float* w4    = (const float*)d_in[9];
    const float* b4    = (const float*)d_in[10];
    float* out = (float*)d_out;

    {
        const int total = 8 * 32 * 8 * 256;
        transpose_grids_h<<<(total + 255) / 256, 256>>>(grid1, grid2);
    }
    const int total = 8 * IMG_H * IMG_W;
    bgrid_fused_kernel<<<total / 256, 256>>>(src,
                                             w1, b1, w2, b2, w3, b3, w4, b4,
                                             out);
}